// round 14
// baseline (speedup 1.0000x reference)
#include <cuda_runtime.h>
#include <math.h>
#include <stdint.h>

#define BSZ 2
#define SEQ 4096
#define DMODEL 512
#define NHEAD 8
#define DHEAD 64
#define MROWS 8192
#define QKVD 1536
#define NBH 16
#define NSPLIT 4                 // split-K quarters

// Device-global scratch — referenced ONLY from device code (host-side symbol
// args bind the host shadow via ATS on GB300: silent zeros).
__device__ float g_QKV[(size_t)MROWS * QKVD];    // [m][1536] (only Q cols written)
__device__ uint32_t g_K16[NBH][SEQ][32];         // fp16x2, perm slots
__device__ uint32_t g_Vtmp[NBH][SEQ][32];        // fp16x2, natural (qkv epilogue)
__device__ uint32_t g_V16[NBH][DHEAD][SEQ / 2];  // fp16x2 transposed, perm slots
__device__ float g_Opart[NSPLIT][(size_t)MROWS * DMODEL];  // unnormalized O parts
__device__ float g_Lpart[NSPLIT][NBH][SEQ];      // row-sum parts

// ---------------------------------------------------------------------------
// Helpers
// ---------------------------------------------------------------------------
__device__ __forceinline__ uint32_t f16x2_of(float x0, float x1) {
    uint32_t d;
    asm("cvt.rn.f16x2.f32 %0, %1, %2;" : "=r"(d) : "f"(x1), "f"(x0));  // x0->low
    return d;
}
__device__ __forceinline__ void mma_fp16(float4& c, const uint32_t a[4],
                                         uint32_t b0, uint32_t b1) {
    asm("mma.sync.aligned.m16n8k16.row.col.f32.f16.f16.f32 "
        "{%0,%1,%2,%3}, {%4,%5,%6,%7}, {%8,%9}, {%0,%1,%2,%3};"
        : "+f"(c.x), "+f"(c.y), "+f"(c.z), "+f"(c.w)
        : "r"(a[0]), "r"(a[1]), "r"(a[2]), "r"(a[3]), "r"(b0), "r"(b1));
}
__device__ __forceinline__ float ex2(float x) {
    float y;
    asm("ex2.approx.f32 %0, %1;" : "=f"(y) : "f"(x));
    return y;
}
__device__ __forceinline__ int perm32(int p) {
    int r = p & 7;
    return (p & ~7) | ((r < 4) ? (2 * r) : (2 * r - 7));
}
__device__ __forceinline__ void cp16(uint32_t saddr, const void* gptr) {
    asm volatile("cp.async.cg.shared.global [%0], [%1], 16;"
                 :: "r"(saddr), "l"(gptr));
}
#define CP_COMMIT() asm volatile("cp.async.commit_group;" ::: "memory")
#define CP_WAIT0()  asm volatile("cp.async.wait_group 0;" ::: "memory")

// ---------------------------------------------------------------------------
// fp16 MMA GEMM mainloop; A-tile loader is a template parameter so out_gemm
// can fuse the (sum Opart)*Linv normalization.
// ---------------------------------------------------------------------------
struct GemmAcc { float4 acc[8]; };

template <typename LoadAFn>
__device__ __forceinline__ void gemm_mainloop(LoadAFn loadA_src,
                                              const float* __restrict__ W,
                                              int Nld, GemmAcc& R)
{
    __shared__ uint32_t Af[128][24];
    __shared__ uint32_t Bf[64][24];

    const int n0 = blockIdx.x * 64;
    const int t = threadIdx.x;
    const int w = t >> 5, lane = t & 31, gid = lane >> 2, tid = lane & 3;

#pragma unroll
    for (int nb = 0; nb < 8; ++nb) R.acc[nb] = make_float4(0.f, 0.f, 0.f, 0.f);

    float2 ax[8], b0r[2], b1r[2];

    auto loadB = [&](int kc) {
#pragma unroll
        for (int rep = 0; rep < 2; ++rep) {
            int kpl = (t >> 5) + rep * 8;
            const float* w0 = W + (size_t)(kc + 2 * kpl) * Nld + n0 + 2 * (t & 31);
            b0r[rep] = *reinterpret_cast<const float2*>(w0);
            b1r[rep] = *reinterpret_cast<const float2*>(w0 + Nld);
        }
    };
    auto store_tiles = [&]() {
        int s = perm32(t & 15);
#pragma unroll
        for (int rep = 0; rep < 8; ++rep) {
            int row = (t >> 4) + rep * 16;
            Af[row][s] = f16x2_of(ax[rep].x, ax[rep].y);
        }
        int np = t & 31;
#pragma unroll
        for (int rep = 0; rep < 2; ++rep) {
            int kpl = (t >> 5) + rep * 8;
            int s2 = perm32(kpl);
            Bf[2 * np][s2]     = f16x2_of(b0r[rep].x, b1r[rep].x);
            Bf[2 * np + 1][s2] = f16x2_of(b0r[rep].y, b1r[rep].y);
        }
    };

    loadA_src(0, ax); loadB(0);
    for (int kc = 0; kc < 512; kc += 32) {
        store_tiles();
        __syncthreads();
        if (kc + 32 < 512) { loadA_src(kc + 32, ax); loadB(kc + 32); }

#pragma unroll
        for (int kk = 0; kk < 2; ++kk) {
            int sb = kk * 8 + 2 * tid;
            uint2 a0 = *reinterpret_cast<const uint2*>(&Af[w * 16 + gid][sb]);
            uint2 a1 = *reinterpret_cast<const uint2*>(&Af[w * 16 + gid + 8][sb]);
            uint32_t af[4] = {a0.x, a1.x, a0.y, a1.y};
#pragma unroll
            for (int nb = 0; nb < 8; ++nb) {
                uint2 b2 = *reinterpret_cast<const uint2*>(&Bf[nb * 8 + gid][sb]);
                mma_fp16(R.acc[nb], af, b2.x, b2.y);
            }
        }
        __syncthreads();
    }
}

// ---------------------------------------------------------------------------
// Kernel 1: qkv = x @ W_qkv + b_qkv. Fused epilogue routes per-region:
//   Q cols -> g_QKV f32;  K cols -> g_K16 fp16 (perm);  V cols -> g_Vtmp fp16.
// ---------------------------------------------------------------------------
__global__ __launch_bounds__(256) void qkv_gemm_mma(const float* __restrict__ X,
                                                    const float* __restrict__ W,
                                                    const float* __restrict__ bias)
{
    const int m0 = blockIdx.y * 128;
    const int t = threadIdx.x;

    auto loadA = [&](int kc, float2 (&ax)[8]) {
#pragma unroll
        for (int rep = 0; rep < 8; ++rep) {
            int row = (t >> 4) + rep * 16;
            ax[rep] = *reinterpret_cast<const float2*>(
                X + (size_t)(m0 + row) * 512 + kc + 2 * (t & 15));
        }
    };

    GemmAcc R;
    gemm_mainloop(loadA, W, QKVD, R);

    const int n0 = blockIdx.x * 64;
    const int w = t >> 5, lane = t & 31, gid = lane >> 2, tid = lane & 3;
    const int reg = n0 >> 9;   // 0:Q 1:K 2:V

#pragma unroll
    for (int nb = 0; nb < 8; ++nb) {
        int n = n0 + nb * 8 + 2 * tid;
        float2 bb = *reinterpret_cast<const float2*>(bias + n);
        int r0 = m0 + w * 16 + gid;
        float vx0 = R.acc[nb].x + bb.x, vy0 = R.acc[nb].y + bb.y;   // row r0
        float vx1 = R.acc[nb].z + bb.x, vy1 = R.acc[nb].w + bb.y;   // row r0+8
        if (reg == 0) {
            *reinterpret_cast<float2*>(g_QKV + (size_t)r0 * QKVD + n) =
                make_float2(vx0, vy0);
            *reinterpret_cast<float2*>(g_QKV + (size_t)(r0 + 8) * QKVD + n) =
                make_float2(vx1, vy1);
        } else {
            int nk = n - (reg << 9);
            int h = nk >> 6, ep = (nk & 63) >> 1;
            int bb2 = r0 >> 12;
            int key = r0 & (SEQ - 1);
            int bhI = bb2 * NHEAD + h;
            if (reg == 1) {
                int s = perm32(ep);
                g_K16[bhI][key][s]     = f16x2_of(vx0, vy0);
                g_K16[bhI][key + 8][s] = f16x2_of(vx1, vy1);
            } else {
                g_Vtmp[bhI][key][ep]     = f16x2_of(vx0, vy0);
                g_Vtmp[bhI][key + 8][ep] = f16x2_of(vx1, vy1);
            }
        }
    }
}

// ---------------------------------------------------------------------------
// Kernel 2: transpose V fp16 -> g_V16 [bh][e][keypair, perm slots]
// ---------------------------------------------------------------------------
__global__ __launch_bounds__(256) void presplit_v()
{
    __shared__ uint32_t Vt[64][33];
    const int bh = blockIdx.y;
    const int key0 = blockIdx.x * 64;
    const int t = threadIdx.x;

#pragma unroll
    for (int j = 0; j < 8; ++j) {
        int idx = t + 256 * j;
        int row = idx >> 5, col = idx & 31;
        Vt[row][col] = g_Vtmp[bh][key0 + row][col];
    }
    __syncthreads();

    const int wv = t >> 5, kp = t & 31;
    const int s = perm32(kp);
#pragma unroll
    for (int i = 0; i < 8; ++i) {
        int e = wv * 8 + i;
        uint32_t a = Vt[2 * kp][e >> 1];
        uint32_t b = Vt[2 * kp + 1][e >> 1];
        uint32_t sel = (e & 1) ? 0x7632u : 0x5410u;
        g_V16[bh][e][blockIdx.x * 32 + s] = __byte_perm(a, b, sel);
    }
}

// ---------------------------------------------------------------------------
// Kernel 3: flash attention, SPLIT-K in QUARTERS. Inner loop identical to
// R11/R13 (128 thr, 32 q-rows/warp); each CTA handles 16 key-tiles.
// Max-free softmax => partials additive, no rescale.
// Grid: 2048 = 16 bh x 32 qt x 4 quarters -> makespan 1.25T on 444 slots.
// ---------------------------------------------------------------------------
#define TILE_U32 2560   // 64*40
#define FL_SMEM (2 * 2 * TILE_U32 * 4)
#define ONES16X2 0x3C003C00u   // (1.0h, 1.0h)

__global__ __launch_bounds__(128, 3) void flash_mma()
{
    extern __shared__ uint32_t dsm[];
    uint32_t* KB = dsm;                 // [2][64][40]
    uint32_t* VB = dsm + 2 * TILE_U32;  // [2][64][40]

    const int bh = blockIdx.x >> 7;
    const int sub = blockIdx.x & 127;
    const int qt = sub >> 2;            // 128-row q tile, 0..31
    const int part = sub & 3;           // key quarter
    const int kt0 = part * 16;          // first 64-key tile of this quarter
    const int b = bh >> 3, h = bh & 7;
    const int t = threadIdx.x;
    const int w = t >> 5, lane = t & 31, gid = lane >> 2, tid = lane & 3;

    const int crow = t & 63;
    const int cc0 = (t >> 6) * 16;      // {0,16}
    const uint32_t k_s = (uint32_t)__cvta_generic_to_shared(KB);
    const uint32_t v_s = (uint32_t)__cvta_generic_to_shared(VB);

    auto stage = [&](int buf, int kt) {
        const uint32_t* ks = &g_K16[bh][(kt0 + kt) * 64 + crow][cc0];
        const uint32_t* vs = &g_V16[bh][crow][(kt0 + kt) * 32 + cc0];
        uint32_t off = (uint32_t)(buf * TILE_U32 + crow * 40 + cc0) * 4;
#pragma unroll
        for (int i = 0; i < 4; ++i) {
            cp16(k_s + off + 16 * i, ks + 4 * i);
            cp16(v_s + off + 16 * i, vs + 4 * i);
        }
    };

    stage(0, 0);
    CP_COMMIT();

    const float SCALE = 0.125f * 1.4426950408889634f;  // 1/sqrt(64) * log2(e)
    uint32_t qfA[4][4], qfB[4][4];
    {
        const float* Qbase = g_QKV +
            (size_t)(b * SEQ + qt * 128 + w * 32 + gid) * QKVD + h * DHEAD;
#pragma unroll
        for (int kk = 0; kk < 4; ++kk) {
            int e0 = kk * 16 + tid * 2;
#pragma unroll
            for (int halfe = 0; halfe < 2; ++halfe) {
                int e = e0 + halfe * 8;
                float2 xA0 = *reinterpret_cast<const float2*>(Qbase + e);
                float2 xA1 = *reinterpret_cast<const float2*>(Qbase + (size_t)8 * QKVD + e);
                float2 xB0 = *reinterpret_cast<const float2*>(Qbase + (size_t)16 * QKVD + e);
                float2 xB1 = *reinterpret_cast<const float2*>(Qbase + (size_t)24 * QKVD + e);
                qfA[kk][halfe * 2 + 0] = f16x2_of(xA0.x * SCALE, xA0.y * SCALE);
                qfA[kk][halfe * 2 + 1] = f16x2_of(xA1.x * SCALE, xA1.y * SCALE);
                qfB[kk][halfe * 2 + 0] = f16x2_of(xB0.x * SCALE, xB0.y * SCALE);
                qfB[kk][halfe * 2 + 1] = f16x2_of(xB1.x * SCALE, xB1.y * SCALE);
            }
        }
    }

    float4 oA[8], oB[8];
#pragma unroll
    for (int nb = 0; nb < 8; ++nb) {
        oA[nb] = make_float4(0.f, 0.f, 0.f, 0.f);
        oB[nb] = make_float4(0.f, 0.f, 0.f, 0.f);
    }
    float4 laccA = make_float4(0.f, 0.f, 0.f, 0.f);
    float4 laccB = make_float4(0.f, 0.f, 0.f, 0.f);

    for (int kt = 0; kt < SEQ / 64 / NSPLIT; ++kt) {    // 16 tiles
        const int buf = kt & 1;
        CP_WAIT0();
        __syncthreads();
        if (kt + 1 < SEQ / 64 / NSPLIT) { stage(buf ^ 1, kt + 1); CP_COMMIT(); }

        const uint32_t* K = KB + buf * TILE_U32;
        const uint32_t* V = VB + buf * TILE_U32;

#pragma unroll
        for (int c = 0; c < 4; ++c) {
            uint2 ka[4], kb[4];
#pragma unroll
            for (int kk = 0; kk < 4; ++kk) {
                int col = kk * 8 + 2 * tid;
                ka[kk] = *reinterpret_cast<const uint2*>(K + (16 * c + gid) * 40 + col);
                kb[kk] = *reinterpret_cast<const uint2*>(K + (16 * c + 8 + gid) * 40 + col);
            }

            float4 s0A = make_float4(0.f, 0.f, 0.f, 0.f);
            float4 s1A = make_float4(0.f, 0.f, 0.f, 0.f);
            float4 s0B = make_float4(0.f, 0.f, 0.f, 0.f);
            float4 s1B = make_float4(0.f, 0.f, 0.f, 0.f);
#pragma unroll
            for (int kk = 0; kk < 4; ++kk) {
                mma_fp16(s0A, qfA[kk], ka[kk].x, ka[kk].y);
                mma_fp16(s0B, qfB[kk], ka[kk].x, ka[kk].y);
                mma_fp16(s1A, qfA[kk], kb[kk].x, kb[kk].y);
                mma_fp16(s1B, qfB[kk], kb[kk].x, kb[kk].y);
            }

            uint32_t pfA[4], pfB[4];
            pfA[0] = f16x2_of(ex2(s0A.x), ex2(s0A.y));
            pfA[1] = f16x2_of(ex2(s0A.z), ex2(s0A.w));
            pfA[2] = f16x2_of(ex2(s1A.x), ex2(s1A.y));
            pfA[3] = f16x2_of(ex2(s1A.z), ex2(s1A.w));
            pfB[0] = f16x2_of(ex2(s0B.x), ex2(s0B.y));
            pfB[1] = f16x2_of(ex2(s0B.z), ex2(s0B.w));
            pfB[2] = f16x2_of(ex2(s1B.x), ex2(s1B.y));
            pfB[3] = f16x2_of(ex2(s1B.z), ex2(s1B.w));

            mma_fp16(laccA, pfA, ONES16X2, ONES16X2);
            mma_fp16(laccB, pfB, ONES16X2, ONES16X2);

#pragma unroll
            for (int nb = 0; nb < 8; ++nb) {
                uint2 v2 = *reinterpret_cast<const uint2*>(
                    V + (nb * 8 + gid) * 40 + c * 8 + 2 * tid);
                mma_fp16(oA[nb], pfA, v2.x, v2.y);
                mma_fp16(oB[nb], pfB, v2.x, v2.y);
            }
        }
    }

    // ---- write UNNORMALIZED partials + row-sum partials ----
    int q0 = qt * 128 + w * 32 + gid;
    float* OP = g_Opart[part];
    float* OrA0 = OP + (size_t)(b * SEQ + q0) * DMODEL + h * DHEAD;
    float* OrA1 = OrA0 + (size_t)8 * DMODEL;
    float* OrB0 = OrA0 + (size_t)16 * DMODEL;
    float* OrB1 = OrA0 + (size_t)24 * DMODEL;
#pragma unroll
    for (int nb = 0; nb < 8; ++nb) {
        int col = nb * 8 + tid * 2;
        *reinterpret_cast<float2*>(OrA0 + col) = make_float2(oA[nb].x, oA[nb].y);
        *reinterpret_cast<float2*>(OrA1 + col) = make_float2(oA[nb].z, oA[nb].w);
        *reinterpret_cast<float2*>(OrB0 + col) = make_float2(oB[nb].x, oB[nb].y);
        *reinterpret_cast<float2*>(OrB1 + col) = make_float2(oB[nb].z, oB[nb].w);
    }
    if (tid == 0) {   // all 4 quad lanes hold identical row sums
        g_Lpart[part][bh][q0]      = laccA.x;
        g_Lpart[part][bh][q0 + 8]  = laccA.z;
        g_Lpart[part][bh][q0 + 16] = laccB.x;
        g_Lpart[part][bh][q0 + 24] = laccB.z;
    }
}

// ---------------------------------------------------------------------------
// Kernel 4: out = ((sum Opart)/(sum Lpart)) @ W_out + b_out — fully fused.
// ---------------------------------------------------------------------------
__global__ __launch_bounds__(256) void out_gemm_mma(const float* __restrict__ W,
                                                    const float* __restrict__ bias,
                                                    float* __restrict__ Y)
{
    const int m0 = blockIdx.y * 128;
    const int t = threadIdx.x;

    auto loadA = [&](int kc, float2 (&ax)[8]) {
        int col = kc + 2 * (t & 15);
        int h = col >> 6;
#pragma unroll
        for (int rep = 0; rep < 8; ++rep) {
            int r = m0 + (t >> 4) + rep * 16;
            size_t idx = (size_t)r * DMODEL + col;
            int bhI = (r >> 12) * NHEAD + h;
            int rr = r & (SEQ - 1);
            float sx = 0.f, sy = 0.f, l = 0.f;
#pragma unroll
            for (int p = 0; p < NSPLIT; ++p) {
                float2 a = *reinterpret_cast<const float2*>(&g_Opart[p][idx]);
                sx += a.x; sy += a.y;
                l += g_Lpart[p][bhI][rr];
            }
            float inv = 1.0f / l;
            ax[rep] = make_float2(sx * inv, sy * inv);
        }
    };

    GemmAcc R;
    gemm_mainloop(loadA, W, DMODEL, R);

    const int n0 = blockIdx.x * 64;
    const int w = t >> 5, lane = t & 31, gid = lane >> 2, tid = lane & 3;

#pragma unroll
    for (int nb = 0; nb < 8; ++nb) {
        int n = n0 + nb * 8 + 2 * tid;
        float2 bb = *reinterpret_cast<const float2*>(bias + n);
        int r0 = m0 + w * 16 + gid;
        *reinterpret_cast<float2*>(Y + (size_t)r0 * DMODEL + n) =
            make_float2(R.acc[nb].x + bb.x, R.acc[nb].y + bb.y);
        *reinterpret_cast<float2*>(Y + (size_t)(r0 + 8) * DMODEL + n) =
            make_float2(R.acc[nb].z + bb.x, R.acc[nb].w + bb.y);
    }
}

// ---------------------------------------------------------------------------
extern "C" void kernel_launch(void* const* d_in, const int* in_sizes, int n_in,
                              void* d_out, int out_size)
{
    const float* x     = (const float*)d_in[0];
    const float* W_qkv = (const float*)d_in[1];
    const float* b_qkv = (const float*)d_in[2];
    const float* W_out = (const float*)d_in[3];
    const float* b_out = (const float*)d_in[4];

    for (int i = 0; i < n_in; ++i) {
        switch (in_sizes[i]) {
            case MROWS * DMODEL:  x     = (const float*)d_in[i]; break;
            case DMODEL * QKVD:   W_qkv = (const float*)d_in[i]; break;
            case QKVD:            b_qkv = (const float*)d_in[i]; break;
            case DMODEL * DMODEL: W_out = (const float*)d_in[i]; break;
            case DMODEL:          b_out = (const float*)d_in[i]; break;
            default: break;
        }
    }
    float* out = (float*)d_out;
    (void)out_size;

    static bool attr_done = false;
    if (!attr_done) {
        cudaFuncSetAttribute(flash_mma,
                             cudaFuncAttributeMaxDynamicSharedMemorySize,
                             FL_SMEM);
        attr_done = true;
    }

    qkv_gemm_mma<<<dim3(QKVD / 64, MROWS / 128), 256>>>(x, W_qkv, b_qkv);
    presplit_v<<<dim3(SEQ / 64, NBH), 256>>>();
    flash_mma<<<NBH * 32 * NSPLIT, 128, FL_SMEM>>>();
    out_gemm_mma<<<dim3(DMODEL / 64, MROWS / 128), 256>>>(W_out, b_out, out);
}

// round 15
// speedup vs baseline: 1.3270x; 1.3270x over previous
#include <cuda_runtime.h>
#include <math.h>
#include <stdint.h>

#define BSZ 2
#define SEQ 4096
#define DMODEL 512
#define NHEAD 8
#define DHEAD 64
#define MROWS 8192
#define QKVD 1536
#define NBH 16
#define NSPLIT 4                 // split-K quarters

// Device-global scratch — referenced ONLY from device code (host-side symbol
// args bind the host shadow via ATS on GB300: silent zeros).
__device__ float g_QKV[(size_t)MROWS * QKVD];    // [m][1536] (only Q cols written)
__device__ float g_O[(size_t)MROWS * DMODEL];    // combined normalized O
__device__ uint32_t g_K16[NBH][SEQ][32];         // fp16x2, perm slots
__device__ uint32_t g_Vtmp[NBH][SEQ][32];        // fp16x2, natural (qkv epilogue)
__device__ uint32_t g_V16[NBH][DHEAD][SEQ / 2];  // fp16x2 transposed, perm slots
__device__ float g_Opart[NSPLIT][(size_t)MROWS * DMODEL];  // unnormalized O parts
__device__ float g_Lpart[NSPLIT][NBH][SEQ];      // row-sum parts

// ---------------------------------------------------------------------------
// Helpers
// ---------------------------------------------------------------------------
__device__ __forceinline__ uint32_t f16x2_of(float x0, float x1) {
    uint32_t d;
    asm("cvt.rn.f16x2.f32 %0, %1, %2;" : "=r"(d) : "f"(x1), "f"(x0));  // x0->low
    return d;
}
__device__ __forceinline__ void mma_fp16(float4& c, const uint32_t a[4],
                                         uint32_t b0, uint32_t b1) {
    asm("mma.sync.aligned.m16n8k16.row.col.f32.f16.f16.f32 "
        "{%0,%1,%2,%3}, {%4,%5,%6,%7}, {%8,%9}, {%0,%1,%2,%3};"
        : "+f"(c.x), "+f"(c.y), "+f"(c.z), "+f"(c.w)
        : "r"(a[0]), "r"(a[1]), "r"(a[2]), "r"(a[3]), "r"(b0), "r"(b1));
}
__device__ __forceinline__ float ex2(float x) {
    float y;
    asm("ex2.approx.f32 %0, %1;" : "=f"(y) : "f"(x));
    return y;
}
__device__ __forceinline__ int perm32(int p) {
    int r = p & 7;
    return (p & ~7) | ((r < 4) ? (2 * r) : (2 * r - 7));
}
__device__ __forceinline__ void cp16(uint32_t saddr, const void* gptr) {
    asm volatile("cp.async.cg.shared.global [%0], [%1], 16;"
                 :: "r"(saddr), "l"(gptr));
}
#define CP_COMMIT() asm volatile("cp.async.commit_group;" ::: "memory")
#define CP_WAIT0()  asm volatile("cp.async.wait_group 0;" ::: "memory")

// ---------------------------------------------------------------------------
// fp16 MMA GEMM mainloop, N-tile 128 (32 MMAs per warp per K-chunk — 2x the
// MMA density per barrier vs the old 64-wide tile; every A-fragment load
// feeds 16 MMAs).
// ---------------------------------------------------------------------------
struct GemmAcc { float4 acc[16]; };

template <typename LoadAFn>
__device__ __forceinline__ void gemm_mainloop(LoadAFn loadA_src,
                                              const float* __restrict__ W,
                                              int Nld, GemmAcc& R)
{
    __shared__ uint32_t Af[128][24];
    __shared__ uint32_t Bf[128][24];

    const int n0 = blockIdx.x * 128;
    const int t = threadIdx.x;
    const int w = t >> 5, lane = t & 31, gid = lane >> 2, tid = lane & 3;

#pragma unroll
    for (int nb = 0; nb < 16; ++nb) R.acc[nb] = make_float4(0.f, 0.f, 0.f, 0.f);

    float2 ax[8], b0r[4], b1r[4];

    auto loadB = [&](int kc) {
#pragma unroll
        for (int rep = 0; rep < 4; ++rep) {
            int kpl = (t >> 6) + rep * 4;            // 0..15
            const float* w0 = W + (size_t)(kc + 2 * kpl) * Nld + n0 + 2 * (t & 63);
            b0r[rep] = *reinterpret_cast<const float2*>(w0);
            b1r[rep] = *reinterpret_cast<const float2*>(w0 + Nld);
        }
    };
    auto store_tiles = [&]() {
        int s = perm32(t & 15);
#pragma unroll
        for (int rep = 0; rep < 8; ++rep) {
            int row = (t >> 4) + rep * 16;
            Af[row][s] = f16x2_of(ax[rep].x, ax[rep].y);
        }
        int np = t & 63;
#pragma unroll
        for (int rep = 0; rep < 4; ++rep) {
            int kpl = (t >> 6) + rep * 4;
            int s2 = perm32(kpl);
            Bf[2 * np][s2]     = f16x2_of(b0r[rep].x, b1r[rep].x);
            Bf[2 * np + 1][s2] = f16x2_of(b0r[rep].y, b1r[rep].y);
        }
    };

    loadA_src(0, ax); loadB(0);
    for (int kc = 0; kc < 512; kc += 32) {
        store_tiles();
        __syncthreads();
        if (kc + 32 < 512) { loadA_src(kc + 32, ax); loadB(kc + 32); }

#pragma unroll
        for (int kk = 0; kk < 2; ++kk) {
            int sb = kk * 8 + 2 * tid;
            uint2 a0 = *reinterpret_cast<const uint2*>(&Af[w * 16 + gid][sb]);
            uint2 a1 = *reinterpret_cast<const uint2*>(&Af[w * 16 + gid + 8][sb]);
            uint32_t af[4] = {a0.x, a1.x, a0.y, a1.y};
#pragma unroll
            for (int nb = 0; nb < 16; ++nb) {
                uint2 b2 = *reinterpret_cast<const uint2*>(&Bf[nb * 8 + gid][sb]);
                mma_fp16(R.acc[nb], af, b2.x, b2.y);
            }
        }
        __syncthreads();
    }
}

// ---------------------------------------------------------------------------
// Kernel 1: qkv = x @ W_qkv + b_qkv. Fused epilogue routes per-region:
//   Q cols -> g_QKV f32;  K cols -> g_K16 fp16 (perm);  V cols -> g_Vtmp fp16.
// (region uniform per block: n0 multiple of 128, boundaries at 512/1024)
// ---------------------------------------------------------------------------
__global__ __launch_bounds__(256) void qkv_gemm_mma(const float* __restrict__ X,
                                                    const float* __restrict__ W,
                                                    const float* __restrict__ bias)
{
    const int m0 = blockIdx.y * 128;
    const int t = threadIdx.x;

    auto loadA = [&](int kc, float2 (&ax)[8]) {
#pragma unroll
        for (int rep = 0; rep < 8; ++rep) {
            int row = (t >> 4) + rep * 16;
            ax[rep] = *reinterpret_cast<const float2*>(
                X + (size_t)(m0 + row) * 512 + kc + 2 * (t & 15));
        }
    };

    GemmAcc R;
    gemm_mainloop(loadA, W, QKVD, R);

    const int n0 = blockIdx.x * 128;
    const int w = t >> 5, lane = t & 31, gid = lane >> 2, tid = lane & 3;
    const int reg = n0 >> 9;   // 0:Q 1:K 2:V (uniform per block)

#pragma unroll
    for (int nb = 0; nb < 16; ++nb) {
        int n = n0 + nb * 8 + 2 * tid;
        float2 bb = *reinterpret_cast<const float2*>(bias + n);
        int r0 = m0 + w * 16 + gid;
        float vx0 = R.acc[nb].x + bb.x, vy0 = R.acc[nb].y + bb.y;   // row r0
        float vx1 = R.acc[nb].z + bb.x, vy1 = R.acc[nb].w + bb.y;   // row r0+8
        if (reg == 0) {
            *reinterpret_cast<float2*>(g_QKV + (size_t)r0 * QKVD + n) =
                make_float2(vx0, vy0);
            *reinterpret_cast<float2*>(g_QKV + (size_t)(r0 + 8) * QKVD + n) =
                make_float2(vx1, vy1);
        } else {
            int nk = n - (reg << 9);
            int h = nk >> 6, ep = (nk & 63) >> 1;
            int bb2 = r0 >> 12;
            int key = r0 & (SEQ - 1);
            int bhI = bb2 * NHEAD + h;
            if (reg == 1) {
                int s = perm32(ep);
                g_K16[bhI][key][s]     = f16x2_of(vx0, vy0);
                g_K16[bhI][key + 8][s] = f16x2_of(vx1, vy1);
            } else {
                g_Vtmp[bhI][key][ep]     = f16x2_of(vx0, vy0);
                g_Vtmp[bhI][key + 8][ep] = f16x2_of(vx1, vy1);
            }
        }
    }
}

// ---------------------------------------------------------------------------
// Kernel 2: transpose V fp16 -> g_V16 [bh][e][keypair, perm slots]
// ---------------------------------------------------------------------------
__global__ __launch_bounds__(256) void presplit_v()
{
    __shared__ uint32_t Vt[64][33];
    const int bh = blockIdx.y;
    const int key0 = blockIdx.x * 64;
    const int t = threadIdx.x;

#pragma unroll
    for (int j = 0; j < 8; ++j) {
        int idx = t + 256 * j;
        int row = idx >> 5, col = idx & 31;
        Vt[row][col] = g_Vtmp[bh][key0 + row][col];
    }
    __syncthreads();

    const int wv = t >> 5, kp = t & 31;
    const int s = perm32(kp);
#pragma unroll
    for (int i = 0; i < 8; ++i) {
        int e = wv * 8 + i;
        uint32_t a = Vt[2 * kp][e >> 1];
        uint32_t b = Vt[2 * kp + 1][e >> 1];
        uint32_t sel = (e & 1) ? 0x7632u : 0x5410u;
        g_V16[bh][e][blockIdx.x * 32 + s] = __byte_perm(a, b, sel);
    }
}

// ---------------------------------------------------------------------------
// Kernel 3: flash attention, SPLIT-K quarters (unchanged from R14 — its gain
// was confirmed by decomposition).
// ---------------------------------------------------------------------------
#define TILE_U32 2560   // 64*40
#define FL_SMEM (2 * 2 * TILE_U32 * 4)
#define ONES16X2 0x3C003C00u   // (1.0h, 1.0h)

__global__ __launch_bounds__(128, 3) void flash_mma()
{
    extern __shared__ uint32_t dsm[];
    uint32_t* KB = dsm;                 // [2][64][40]
    uint32_t* VB = dsm + 2 * TILE_U32;  // [2][64][40]

    const int bh = blockIdx.x >> 7;
    const int sub = blockIdx.x & 127;
    const int qt = sub >> 2;            // 128-row q tile, 0..31
    const int part = sub & 3;           // key quarter
    const int kt0 = part * 16;
    const int b = bh >> 3, h = bh & 7;
    const int t = threadIdx.x;
    const int w = t >> 5, lane = t & 31, gid = lane >> 2, tid = lane & 3;

    const int crow = t & 63;
    const int cc0 = (t >> 6) * 16;      // {0,16}
    const uint32_t k_s = (uint32_t)__cvta_generic_to_shared(KB);
    const uint32_t v_s = (uint32_t)__cvta_generic_to_shared(VB);

    auto stage = [&](int buf, int kt) {
        const uint32_t* ks = &g_K16[bh][(kt0 + kt) * 64 + crow][cc0];
        const uint32_t* vs = &g_V16[bh][crow][(kt0 + kt) * 32 + cc0];
        uint32_t off = (uint32_t)(buf * TILE_U32 + crow * 40 + cc0) * 4;
#pragma unroll
        for (int i = 0; i < 4; ++i) {
            cp16(k_s + off + 16 * i, ks + 4 * i);
            cp16(v_s + off + 16 * i, vs + 4 * i);
        }
    };

    stage(0, 0);
    CP_COMMIT();

    const float SCALE = 0.125f * 1.4426950408889634f;  // 1/sqrt(64) * log2(e)
    uint32_t qfA[4][4], qfB[4][4];
    {
        const float* Qbase = g_QKV +
            (size_t)(b * SEQ + qt * 128 + w * 32 + gid) * QKVD + h * DHEAD;
#pragma unroll
        for (int kk = 0; kk < 4; ++kk) {
            int e0 = kk * 16 + tid * 2;
#pragma unroll
            for (int halfe = 0; halfe < 2; ++halfe) {
                int e = e0 + halfe * 8;
                float2 xA0 = *reinterpret_cast<const float2*>(Qbase + e);
                float2 xA1 = *reinterpret_cast<const float2*>(Qbase + (size_t)8 * QKVD + e);
                float2 xB0 = *reinterpret_cast<const float2*>(Qbase + (size_t)16 * QKVD + e);
                float2 xB1 = *reinterpret_cast<const float2*>(Qbase + (size_t)24 * QKVD + e);
                qfA[kk][halfe * 2 + 0] = f16x2_of(xA0.x * SCALE, xA0.y * SCALE);
                qfA[kk][halfe * 2 + 1] = f16x2_of(xA1.x * SCALE, xA1.y * SCALE);
                qfB[kk][halfe * 2 + 0] = f16x2_of(xB0.x * SCALE, xB0.y * SCALE);
                qfB[kk][halfe * 2 + 1] = f16x2_of(xB1.x * SCALE, xB1.y * SCALE);
            }
        }
    }

    float4 oA[8], oB[8];
#pragma unroll
    for (int nb = 0; nb < 8; ++nb) {
        oA[nb] = make_float4(0.f, 0.f, 0.f, 0.f);
        oB[nb] = make_float4(0.f, 0.f, 0.f, 0.f);
    }
    float4 laccA = make_float4(0.f, 0.f, 0.f, 0.f);
    float4 laccB = make_float4(0.f, 0.f, 0.f, 0.f);

    for (int kt = 0; kt < SEQ / 64 / NSPLIT; ++kt) {    // 16 tiles
        const int buf = kt & 1;
        CP_WAIT0();
        __syncthreads();
        if (kt + 1 < SEQ / 64 / NSPLIT) { stage(buf ^ 1, kt + 1); CP_COMMIT(); }

        const uint32_t* K = KB + buf * TILE_U32;
        const uint32_t* V = VB + buf * TILE_U32;

#pragma unroll
        for (int c = 0; c < 4; ++c) {
            uint2 ka[4], kb[4];
#pragma unroll
            for (int kk = 0; kk < 4; ++kk) {
                int col = kk * 8 + 2 * tid;
                ka[kk] = *reinterpret_cast<const uint2*>(K + (16 * c + gid) * 40 + col);
                kb[kk] = *reinterpret_cast<const uint2*>(K + (16 * c + 8 + gid) * 40 + col);
            }

            float4 s0A = make_float4(0.f, 0.f, 0.f, 0.f);
            float4 s1A = make_float4(0.f, 0.f, 0.f, 0.f);
            float4 s0B = make_float4(0.f, 0.f, 0.f, 0.f);
            float4 s1B = make_float4(0.f, 0.f, 0.f, 0.f);
#pragma unroll
            for (int kk = 0; kk < 4; ++kk) {
                mma_fp16(s0A, qfA[kk], ka[kk].x, ka[kk].y);
                mma_fp16(s0B, qfB[kk], ka[kk].x, ka[kk].y);
                mma_fp16(s1A, qfA[kk], kb[kk].x, kb[kk].y);
                mma_fp16(s1B, qfB[kk], kb[kk].x, kb[kk].y);
            }

            uint32_t pfA[4], pfB[4];
            pfA[0] = f16x2_of(ex2(s0A.x), ex2(s0A.y));
            pfA[1] = f16x2_of(ex2(s0A.z), ex2(s0A.w));
            pfA[2] = f16x2_of(ex2(s1A.x), ex2(s1A.y));
            pfA[3] = f16x2_of(ex2(s1A.z), ex2(s1A.w));
            pfB[0] = f16x2_of(ex2(s0B.x), ex2(s0B.y));
            pfB[1] = f16x2_of(ex2(s0B.z), ex2(s0B.w));
            pfB[2] = f16x2_of(ex2(s1B.x), ex2(s1B.y));
            pfB[3] = f16x2_of(ex2(s1B.z), ex2(s1B.w));

            mma_fp16(laccA, pfA, ONES16X2, ONES16X2);
            mma_fp16(laccB, pfB, ONES16X2, ONES16X2);

#pragma unroll
            for (int nb = 0; nb < 8; ++nb) {
                uint2 v2 = *reinterpret_cast<const uint2*>(
                    V + (nb * 8 + gid) * 40 + c * 8 + 2 * tid);
                mma_fp16(oA[nb], pfA, v2.x, v2.y);
                mma_fp16(oB[nb], pfB, v2.x, v2.y);
            }
        }
    }

    // ---- write UNNORMALIZED partials + row-sum partials ----
    int q0 = qt * 128 + w * 32 + gid;
    float* OP = g_Opart[part];
    float* OrA0 = OP + (size_t)(b * SEQ + q0) * DMODEL + h * DHEAD;
    float* OrA1 = OrA0 + (size_t)8 * DMODEL;
    float* OrB0 = OrA0 + (size_t)16 * DMODEL;
    float* OrB1 = OrA0 + (size_t)24 * DMODEL;
#pragma unroll
    for (int nb = 0; nb < 8; ++nb) {
        int col = nb * 8 + tid * 2;
        *reinterpret_cast<float2*>(OrA0 + col) = make_float2(oA[nb].x, oA[nb].y);
        *reinterpret_cast<float2*>(OrA1 + col) = make_float2(oA[nb].z, oA[nb].w);
        *reinterpret_cast<float2*>(OrB0 + col) = make_float2(oB[nb].x, oB[nb].y);
        *reinterpret_cast<float2*>(OrB1 + col) = make_float2(oB[nb].z, oB[nb].w);
    }
    if (tid == 0) {
        g_Lpart[part][bh][q0]      = laccA.x;
        g_Lpart[part][bh][q0 + 8]  = laccA.z;
        g_Lpart[part][bh][q0 + 16] = laccB.x;
        g_Lpart[part][bh][q0 + 24] = laccB.z;
    }
}

// ---------------------------------------------------------------------------
// Kernel 4: combine — g_O = (sum_p Opart) / (sum_p Lpart). One pass.
// ---------------------------------------------------------------------------
__global__ __launch_bounds__(256) void combine_o()
{
    size_t idx = ((size_t)blockIdx.x * 256 + threadIdx.x);   // float4 index
    int col4 = (int)(idx & 127);          // 128 float4 per row
    int r = (int)(idx >> 7);
    int h = (col4 * 4) >> 6;
    int bhI = (r >> 12) * NHEAD + h;
    int rr = r & (SEQ - 1);

    float l = 0.f;
    float4 s = make_float4(0.f, 0.f, 0.f, 0.f);
#pragma unroll
    for (int p = 0; p < NSPLIT; ++p) {
        float4 a = *reinterpret_cast<const float4*>(&g_Opart[p][idx * 4]);
        s.x += a.x; s.y += a.y; s.z += a.z; s.w += a.w;
        l += g_Lpart[p][bhI][rr];
    }
    float inv = 1.0f / l;
    *reinterpret_cast<float4*>(&g_O[idx * 4]) =
        make_float4(s.x * inv, s.y * inv, s.z * inv, s.w * inv);
}

// ---------------------------------------------------------------------------
// Kernel 5: out = g_O @ W_out + b_out (plain A-loader — combine already done)
// ---------------------------------------------------------------------------
__global__ __launch_bounds__(256) void out_gemm_mma(const float* __restrict__ W,
                                                    const float* __restrict__ bias,
                                                    float* __restrict__ Y)
{
    const int m0 = blockIdx.y * 128;
    const int t = threadIdx.x;

    auto loadA = [&](int kc, float2 (&ax)[8]) {
#pragma unroll
        for (int rep = 0; rep < 8; ++rep) {
            int row = (t >> 4) + rep * 16;
            ax[rep] = *reinterpret_cast<const float2*>(
                g_O + (size_t)(m0 + row) * 512 + kc + 2 * (t & 15));
        }
    };

    GemmAcc R;
    gemm_mainloop(loadA, W, DMODEL, R);

    const int n0 = blockIdx.x * 128;
    const int w = t >> 5, lane = t & 31, gid = lane >> 2, tid = lane & 3;

#pragma unroll
    for (int nb = 0; nb < 16; ++nb) {
        int n = n0 + nb * 8 + 2 * tid;
        float2 bb = *reinterpret_cast<const float2*>(bias + n);
        int r0 = m0 + w * 16 + gid;
        *reinterpret_cast<float2*>(Y + (size_t)r0 * DMODEL + n) =
            make_float2(R.acc[nb].x + bb.x, R.acc[nb].y + bb.y);
        *reinterpret_cast<float2*>(Y + (size_t)(r0 + 8) * DMODEL + n) =
            make_float2(R.acc[nb].z + bb.x, R.acc[nb].w + bb.y);
    }
}

// ---------------------------------------------------------------------------
extern "C" void kernel_launch(void* const* d_in, const int* in_sizes, int n_in,
                              void* d_out, int out_size)
{
    const float* x     = (const float*)d_in[0];
    const float* W_qkv = (const float*)d_in[1];
    const float* b_qkv = (const float*)d_in[2];
    const float* W_out = (const float*)d_in[3];
    const float* b_out = (const float*)d_in[4];

    for (int i = 0; i < n_in; ++i) {
        switch (in_sizes[i]) {
            case MROWS * DMODEL:  x     = (const float*)d_in[i]; break;
            case DMODEL * QKVD:   W_qkv = (const float*)d_in[i]; break;
            case QKVD:            b_qkv = (const float*)d_in[i]; break;
            case DMODEL * DMODEL: W_out = (const float*)d_in[i]; break;
            case DMODEL:          b_out = (const float*)d_in[i]; break;
            default: break;
        }
    }
    float* out = (float*)d_out;
    (void)out_size;

    static bool attr_done = false;
    if (!attr_done) {
        cudaFuncSetAttribute(flash_mma,
                             cudaFuncAttributeMaxDynamicSharedMemorySize,
                             FL_SMEM);
        attr_done = true;
    }

    qkv_gemm_mma<<<dim3(QKVD / 128, MROWS / 128), 256>>>(x, W_qkv, b_qkv);
    presplit_v<<<dim3(SEQ / 64, NBH), 256>>>();
    flash_mma<<<NBH * 32 * NSPLIT, 128, FL_SMEM>>>();
    combine_o<<<(MROWS * DMODEL / 4) / 256, 256>>>();
    out_gemm_mma<<<dim3(DMODEL / 128, MROWS / 128), 256>>>(W_out, b_out, out);
}

// round 16
// speedup vs baseline: 1.4098x; 1.0624x over previous
#include <cuda_runtime.h>
#include <math.h>
#include <stdint.h>

#define BSZ 2
#define SEQ 4096
#define DMODEL 512
#define NHEAD 8
#define DHEAD 64
#define MROWS 8192
#define QKVD 1536
#define NBH 16
#define NSPLIT 4                 // split-K quarters

// Device-global scratch — referenced ONLY from device code (host-side symbol
// args bind the host shadow via ATS on GB300: silent zeros).
__device__ float g_QKV[(size_t)MROWS * QKVD];    // [m][1536] (only Q cols written)
__device__ uint32_t g_K16[NBH][SEQ][32];         // fp16x2, perm slots
__device__ uint32_t g_Vtmp[NBH][SEQ][32];        // fp16x2, natural (qkv epilogue)
__device__ uint32_t g_V16[NBH][DHEAD][SEQ / 2];  // fp16x2 transposed, perm slots
__device__ float g_Opart[NSPLIT][(size_t)MROWS * DMODEL];  // unnormalized O parts
__device__ float g_Lpart[NSPLIT][NBH][SEQ];      // row-sum parts
// fp16 MMA-ready operands: [row][chunk*16 + perm32(kpair)] (256 u32 per row)
__device__ uint32_t g_X16[(size_t)MROWS * 256];   // x
__device__ uint32_t g_Wq16[(size_t)QKVD * 256];   // W_qkv^T pairs
__device__ uint32_t g_Wo16[(size_t)DMODEL * 256]; // W_out^T pairs
__device__ uint32_t g_O16[(size_t)MROWS * 256];   // combined O (from combine_o)

// ---------------------------------------------------------------------------
// Helpers
// ---------------------------------------------------------------------------
__device__ __forceinline__ uint32_t f16x2_of(float x0, float x1) {
    uint32_t d;
    asm("cvt.rn.f16x2.f32 %0, %1, %2;" : "=r"(d) : "f"(x1), "f"(x0));  // x0->low
    return d;
}
__device__ __forceinline__ void mma_fp16(float4& c, const uint32_t a[4],
                                         uint32_t b0, uint32_t b1) {
    asm("mma.sync.aligned.m16n8k16.row.col.f32.f16.f16.f32 "
        "{%0,%1,%2,%3}, {%4,%5,%6,%7}, {%8,%9}, {%0,%1,%2,%3};"
        : "+f"(c.x), "+f"(c.y), "+f"(c.z), "+f"(c.w)
        : "r"(a[0]), "r"(a[1]), "r"(a[2]), "r"(a[3]), "r"(b0), "r"(b1));
}
__device__ __forceinline__ float ex2(float x) {
    float y;
    asm("ex2.approx.f32 %0, %1;" : "=f"(y) : "f"(x));
    return y;
}
__device__ __forceinline__ int perm32(int p) {
    int r = p & 7;
    return (p & ~7) | ((r < 4) ? (2 * r) : (2 * r - 7));
}
__device__ __forceinline__ void cp16(uint32_t saddr, const void* gptr) {
    asm volatile("cp.async.cg.shared.global [%0], [%1], 16;"
                 :: "r"(saddr), "l"(gptr));
}
#define CP_COMMIT() asm volatile("cp.async.commit_group;" ::: "memory")
#define CP_WAIT0()  asm volatile("cp.async.wait_group 0;" ::: "memory")

// ---------------------------------------------------------------------------
// Operand pre-conversion kernels (once per launch; all rounding identical to
// the old in-loop conversions, just hoisted).
// ---------------------------------------------------------------------------
__global__ __launch_bounds__(256) void convert_x(const float* __restrict__ X)
{
    int idx = blockIdx.x * 256 + threadIdx.x;   // < MROWS*256
    int m = idx >> 8, p = idx & 255;
    int chunk = p >> 4, kpl = p & 15;
    float2 v = *reinterpret_cast<const float2*>(
        X + (size_t)m * 512 + chunk * 32 + 2 * kpl);
    g_X16[(size_t)m * 256 + chunk * 16 + perm32(kpl)] = f16x2_of(v.x, v.y);
}

__global__ __launch_bounds__(256) void convert_wq(const float* __restrict__ W)
{
    int kp = blockIdx.x;                        // 0..255 k-pairs
    int chunk = kp >> 4, kpl = kp & 15;
    int s = perm32(kpl);
    int k = chunk * 32 + 2 * kpl;
    for (int n = threadIdx.x; n < QKVD; n += 256) {
        float a = W[(size_t)k * QKVD + n];
        float b = W[(size_t)(k + 1) * QKVD + n];
        g_Wq16[(size_t)n * 256 + chunk * 16 + s] = f16x2_of(a, b);
    }
}

__global__ __launch_bounds__(256) void convert_wo(const float* __restrict__ W)
{
    int kp = blockIdx.x;
    int chunk = kp >> 4, kpl = kp & 15;
    int s = perm32(kpl);
    int k = chunk * 32 + 2 * kpl;
    for (int n = threadIdx.x; n < DMODEL; n += 256) {
        float a = W[(size_t)k * DMODEL + n];
        float b = W[(size_t)(k + 1) * DMODEL + n];
        g_Wo16[(size_t)n * 256 + chunk * 16 + s] = f16x2_of(a, b);
    }
}

// ---------------------------------------------------------------------------
// fp16 GEMM mainloop, all-fp16 operands, cp.async double-buffered staging,
// one barrier per K-chunk. Tile 128x128, 256 threads, 32 MMAs/warp/chunk.
// ---------------------------------------------------------------------------
struct GemmAcc { float4 acc[16]; };

__device__ __forceinline__ void gemm16(const uint32_t* __restrict__ A16,
                                       const uint32_t* __restrict__ B16,
                                       int m0, int n0, GemmAcc& R)
{
    __shared__ uint32_t Af[2][128][20];
    __shared__ uint32_t Bf[2][128][20];

    const int t = threadIdx.x;
    const int w = t >> 5, lane = t & 31, gid = lane >> 2, tid = lane & 3;

#pragma unroll
    for (int nb = 0; nb < 16; ++nb) R.acc[nb] = make_float4(0.f, 0.f, 0.f, 0.f);

    const uint32_t af_s = (uint32_t)__cvta_generic_to_shared(&Af[0][0][0]);
    const uint32_t bf_s = (uint32_t)__cvta_generic_to_shared(&Bf[0][0][0]);
    const int srow = t >> 1, shalf = (t & 1) * 8;

    auto stage = [&](int buf, int chunk) {
        uint32_t soff = (uint32_t)((buf * 128 + srow) * 20 + shalf) * 4;
        const uint32_t* asrc = A16 + (size_t)(m0 + srow) * 256 + chunk * 16 + shalf;
        const uint32_t* bsrc = B16 + (size_t)(n0 + srow) * 256 + chunk * 16 + shalf;
        cp16(af_s + soff, asrc); cp16(af_s + soff + 16, asrc + 4);
        cp16(bf_s + soff, bsrc); cp16(bf_s + soff + 16, bsrc + 4);
    };

    stage(0, 0);
    CP_COMMIT();

    for (int chunk = 0; chunk < 16; ++chunk) {
        const int buf = chunk & 1;
        CP_WAIT0();
        __syncthreads();
        if (chunk + 1 < 16) { stage(buf ^ 1, chunk + 1); CP_COMMIT(); }

#pragma unroll
        for (int kk = 0; kk < 2; ++kk) {
            int sb = kk * 8 + 2 * tid;
            uint2 a0 = *reinterpret_cast<const uint2*>(&Af[buf][w * 16 + gid][sb]);
            uint2 a1 = *reinterpret_cast<const uint2*>(&Af[buf][w * 16 + gid + 8][sb]);
            uint32_t af[4] = {a0.x, a1.x, a0.y, a1.y};
#pragma unroll
            for (int nb = 0; nb < 16; ++nb) {
                uint2 b2 = *reinterpret_cast<const uint2*>(&Bf[buf][nb * 8 + gid][sb]);
                mma_fp16(R.acc[nb], af, b2.x, b2.y);
            }
        }
    }
}

// ---------------------------------------------------------------------------
// Kernel: qkv = x @ W_qkv + b_qkv. Epilogue routes per-region:
//   Q cols -> g_QKV f32;  K cols -> g_K16 fp16 (perm);  V cols -> g_Vtmp fp16.
// ---------------------------------------------------------------------------
__global__ __launch_bounds__(256) void qkv_gemm_mma(const float* __restrict__ bias)
{
    const int m0 = blockIdx.y * 128;
    const int n0 = blockIdx.x * 128;
    const int t = threadIdx.x;

    GemmAcc R;
    gemm16(g_X16, g_Wq16, m0, n0, R);

    const int w = t >> 5, lane = t & 31, gid = lane >> 2, tid = lane & 3;
    const int reg = n0 >> 9;   // 0:Q 1:K 2:V (uniform per block)

#pragma unroll
    for (int nb = 0; nb < 16; ++nb) {
        int n = n0 + nb * 8 + 2 * tid;
        float2 bb = *reinterpret_cast<const float2*>(bias + n);
        int r0 = m0 + w * 16 + gid;
        float vx0 = R.acc[nb].x + bb.x, vy0 = R.acc[nb].y + bb.y;   // row r0
        float vx1 = R.acc[nb].z + bb.x, vy1 = R.acc[nb].w + bb.y;   // row r0+8
        if (reg == 0) {
            *reinterpret_cast<float2*>(g_QKV + (size_t)r0 * QKVD + n) =
                make_float2(vx0, vy0);
            *reinterpret_cast<float2*>(g_QKV + (size_t)(r0 + 8) * QKVD + n) =
                make_float2(vx1, vy1);
        } else {
            int nk = n - (reg << 9);
            int h = nk >> 6, ep = (nk & 63) >> 1;
            int bb2 = r0 >> 12;
            int key = r0 & (SEQ - 1);
            int bhI = bb2 * NHEAD + h;
            if (reg == 1) {
                int s = perm32(ep);
                g_K16[bhI][key][s]     = f16x2_of(vx0, vy0);
                g_K16[bhI][key + 8][s] = f16x2_of(vx1, vy1);
            } else {
                g_Vtmp[bhI][key][ep]     = f16x2_of(vx0, vy0);
                g_Vtmp[bhI][key + 8][ep] = f16x2_of(vx1, vy1);
            }
        }
    }
}

// ---------------------------------------------------------------------------
// transpose V fp16 -> g_V16 [bh][e][keypair, perm slots]
// ---------------------------------------------------------------------------
__global__ __launch_bounds__(256) void presplit_v()
{
    __shared__ uint32_t Vt[64][33];
    const int bh = blockIdx.y;
    const int key0 = blockIdx.x * 64;
    const int t = threadIdx.x;

#pragma unroll
    for (int j = 0; j < 8; ++j) {
        int idx = t + 256 * j;
        int row = idx >> 5, col = idx & 31;
        Vt[row][col] = g_Vtmp[bh][key0 + row][col];
    }
    __syncthreads();

    const int wv = t >> 5, kp = t & 31;
    const int s = perm32(kp);
#pragma unroll
    for (int i = 0; i < 8; ++i) {
        int e = wv * 8 + i;
        uint32_t a = Vt[2 * kp][e >> 1];
        uint32_t b = Vt[2 * kp + 1][e >> 1];
        uint32_t sel = (e & 1) ? 0x7632u : 0x5410u;
        g_V16[bh][e][blockIdx.x * 32 + s] = __byte_perm(a, b, sel);
    }
}

// ---------------------------------------------------------------------------
// flash attention, SPLIT-K quarters (unchanged from R14/R15)
// ---------------------------------------------------------------------------
#define TILE_U32 2560   // 64*40
#define FL_SMEM (2 * 2 * TILE_U32 * 4)
#define ONES16X2 0x3C003C00u   // (1.0h, 1.0h)

__global__ __launch_bounds__(128, 3) void flash_mma()
{
    extern __shared__ uint32_t dsm[];
    uint32_t* KB = dsm;                 // [2][64][40]
    uint32_t* VB = dsm + 2 * TILE_U32;  // [2][64][40]

    const int bh = blockIdx.x >> 7;
    const int sub = blockIdx.x & 127;
    const int qt = sub >> 2;            // 128-row q tile, 0..31
    const int part = sub & 3;           // key quarter
    const int kt0 = part * 16;
    const int b = bh >> 3, h = bh & 7;
    const int t = threadIdx.x;
    const int w = t >> 5, lane = t & 31, gid = lane >> 2, tid = lane & 3;

    const int crow = t & 63;
    const int cc0 = (t >> 6) * 16;      // {0,16}
    const uint32_t k_s = (uint32_t)__cvta_generic_to_shared(KB);
    const uint32_t v_s = (uint32_t)__cvta_generic_to_shared(VB);

    auto stage = [&](int buf, int kt) {
        const uint32_t* ks = &g_K16[bh][(kt0 + kt) * 64 + crow][cc0];
        const uint32_t* vs = &g_V16[bh][crow][(kt0 + kt) * 32 + cc0];
        uint32_t off = (uint32_t)(buf * TILE_U32 + crow * 40 + cc0) * 4;
#pragma unroll
        for (int i = 0; i < 4; ++i) {
            cp16(k_s + off + 16 * i, ks + 4 * i);
            cp16(v_s + off + 16 * i, vs + 4 * i);
        }
    };

    stage(0, 0);
    CP_COMMIT();

    const float SCALE = 0.125f * 1.4426950408889634f;  // 1/sqrt(64) * log2(e)
    uint32_t qfA[4][4], qfB[4][4];
    {
        const float* Qbase = g_QKV +
            (size_t)(b * SEQ + qt * 128 + w * 32 + gid) * QKVD + h * DHEAD;
#pragma unroll
        for (int kk = 0; kk < 4; ++kk) {
            int e0 = kk * 16 + tid * 2;
#pragma unroll
            for (int halfe = 0; halfe < 2; ++halfe) {
                int e = e0 + halfe * 8;
                float2 xA0 = *reinterpret_cast<const float2*>(Qbase + e);
                float2 xA1 = *reinterpret_cast<const float2*>(Qbase + (size_t)8 * QKVD + e);
                float2 xB0 = *reinterpret_cast<const float2*>(Qbase + (size_t)16 * QKVD + e);
                float2 xB1 = *reinterpret_cast<const float2*>(Qbase + (size_t)24 * QKVD + e);
                qfA[kk][halfe * 2 + 0] = f16x2_of(xA0.x * SCALE, xA0.y * SCALE);
                qfA[kk][halfe * 2 + 1] = f16x2_of(xA1.x * SCALE, xA1.y * SCALE);
                qfB[kk][halfe * 2 + 0] = f16x2_of(xB0.x * SCALE, xB0.y * SCALE);
                qfB[kk][halfe * 2 + 1] = f16x2_of(xB1.x * SCALE, xB1.y * SCALE);
            }
        }
    }

    float4 oA[8], oB[8];
#pragma unroll
    for (int nb = 0; nb < 8; ++nb) {
        oA[nb] = make_float4(0.f, 0.f, 0.f, 0.f);
        oB[nb] = make_float4(0.f, 0.f, 0.f, 0.f);
    }
    float4 laccA = make_float4(0.f, 0.f, 0.f, 0.f);
    float4 laccB = make_float4(0.f, 0.f, 0.f, 0.f);

    for (int kt = 0; kt < SEQ / 64 / NSPLIT; ++kt) {    // 16 tiles
        const int buf = kt & 1;
        CP_WAIT0();
        __syncthreads();
        if (kt + 1 < SEQ / 64 / NSPLIT) { stage(buf ^ 1, kt + 1); CP_COMMIT(); }

        const uint32_t* K = KB + buf * TILE_U32;
        const uint32_t* V = VB + buf * TILE_U32;

#pragma unroll
        for (int c = 0; c < 4; ++c) {
            uint2 ka[4], kb[4];
#pragma unroll
            for (int kk = 0; kk < 4; ++kk) {
                int col = kk * 8 + 2 * tid;
                ka[kk] = *reinterpret_cast<const uint2*>(K + (16 * c + gid) * 40 + col);
                kb[kk] = *reinterpret_cast<const uint2*>(K + (16 * c + 8 + gid) * 40 + col);
            }

            float4 s0A = make_float4(0.f, 0.f, 0.f, 0.f);
            float4 s1A = make_float4(0.f, 0.f, 0.f, 0.f);
            float4 s0B = make_float4(0.f, 0.f, 0.f, 0.f);
            float4 s1B = make_float4(0.f, 0.f, 0.f, 0.f);
#pragma unroll
            for (int kk = 0; kk < 4; ++kk) {
                mma_fp16(s0A, qfA[kk], ka[kk].x, ka[kk].y);
                mma_fp16(s0B, qfB[kk], ka[kk].x, ka[kk].y);
                mma_fp16(s1A, qfA[kk], kb[kk].x, kb[kk].y);
                mma_fp16(s1B, qfB[kk], kb[kk].x, kb[kk].y);
            }

            uint32_t pfA[4], pfB[4];
            pfA[0] = f16x2_of(ex2(s0A.x), ex2(s0A.y));
            pfA[1] = f16x2_of(ex2(s0A.z), ex2(s0A.w));
            pfA[2] = f16x2_of(ex2(s1A.x), ex2(s1A.y));
            pfA[3] = f16x2_of(ex2(s1A.z), ex2(s1A.w));
            pfB[0] = f16x2_of(ex2(s0B.x), ex2(s0B.y));
            pfB[1] = f16x2_of(ex2(s0B.z), ex2(s0B.w));
            pfB[2] = f16x2_of(ex2(s1B.x), ex2(s1B.y));
            pfB[3] = f16x2_of(ex2(s1B.z), ex2(s1B.w));

            mma_fp16(laccA, pfA, ONES16X2, ONES16X2);
            mma_fp16(laccB, pfB, ONES16X2, ONES16X2);

#pragma unroll
            for (int nb = 0; nb < 8; ++nb) {
                uint2 v2 = *reinterpret_cast<const uint2*>(
                    V + (nb * 8 + gid) * 40 + c * 8 + 2 * tid);
                mma_fp16(oA[nb], pfA, v2.x, v2.y);
                mma_fp16(oB[nb], pfB, v2.x, v2.y);
            }
        }
    }

    // ---- write UNNORMALIZED partials + row-sum partials ----
    int q0 = qt * 128 + w * 32 + gid;
    float* OP = g_Opart[part];
    float* OrA0 = OP + (size_t)(b * SEQ + q0) * DMODEL + h * DHEAD;
    float* OrA1 = OrA0 + (size_t)8 * DMODEL;
    float* OrB0 = OrA0 + (size_t)16 * DMODEL;
    float* OrB1 = OrA0 + (size_t)24 * DMODEL;
#pragma unroll
    for (int nb = 0; nb < 8; ++nb) {
        int col = nb * 8 + tid * 2;
        *reinterpret_cast<float2*>(OrA0 + col) = make_float2(oA[nb].x, oA[nb].y);
        *reinterpret_cast<float2*>(OrA1 + col) = make_float2(oA[nb].z, oA[nb].w);
        *reinterpret_cast<float2*>(OrB0 + col) = make_float2(oB[nb].x, oB[nb].y);
        *reinterpret_cast<float2*>(OrB1 + col) = make_float2(oB[nb].z, oB[nb].w);
    }
    if (tid == 0) {
        g_Lpart[part][bh][q0]      = laccA.x;
        g_Lpart[part][bh][q0 + 8]  = laccA.z;
        g_Lpart[part][bh][q0 + 16] = laccB.x;
        g_Lpart[part][bh][q0 + 24] = laccB.z;
    }
}

// ---------------------------------------------------------------------------
// combine — g_O16 = fp16[(sum_p Opart) / (sum_p Lpart)] in perm-pair layout.
// ---------------------------------------------------------------------------
__global__ __launch_bounds__(256) void combine_o()
{
    size_t idx = ((size_t)blockIdx.x * 256 + threadIdx.x);   // float4 index
    int col4 = (int)(idx & 127);          // 128 float4 per row
    int r = (int)(idx >> 7);
    int h = (col4 * 4) >> 6;
    int bhI = (r >> 12) * NHEAD + h;
    int rr = r & (SEQ - 1);

    float l = 0.f;
    float4 s = make_float4(0.f, 0.f, 0.f, 0.f);
#pragma unroll
    for (int p = 0; p < NSPLIT; ++p) {
        float4 a = *reinterpret_cast<const float4*>(&g_Opart[p][idx * 4]);
        s.x += a.x; s.y += a.y; s.z += a.z; s.w += a.w;
        l += g_Lpart[p][bhI][rr];
    }
    float inv = 1.0f / l;
    // fp16 perm-pair layout: cols 4c..4c+3 = k-pairs 2c, 2c+1 of chunk c>>3
    int chunk = col4 >> 3;
    int kpl0 = (col4 & 7) * 2;
    g_O16[(size_t)r * 256 + chunk * 16 + perm32(kpl0)]     = f16x2_of(s.x * inv, s.y * inv);
    g_O16[(size_t)r * 256 + chunk * 16 + perm32(kpl0 + 1)] = f16x2_of(s.z * inv, s.w * inv);
}

// ---------------------------------------------------------------------------
// out = O @ W_out + b_out (all-fp16 cp.async mainloop)
// ---------------------------------------------------------------------------
__global__ __launch_bounds__(256) void out_gemm_mma(const float* __restrict__ bias,
                                                    float* __restrict__ Y)
{
    const int m0 = blockIdx.y * 128;
    const int n0 = blockIdx.x * 128;
    const int t = threadIdx.x;

    GemmAcc R;
    gemm16(g_O16, g_Wo16, m0, n0, R);

    const int w = t >> 5, lane = t & 31, gid = lane >> 2, tid = lane & 3;

#pragma unroll
    for (int nb = 0; nb < 16; ++nb) {
        int n = n0 + nb * 8 + 2 * tid;
        float2 bb = *reinterpret_cast<const float2*>(bias + n);
        int r0 = m0 + w * 16 + gid;
        *reinterpret_cast<float2*>(Y + (size_t)r0 * DMODEL + n) =
            make_float2(R.acc[nb].x + bb.x, R.acc[nb].y + bb.y);
        *reinterpret_cast<float2*>(Y + (size_t)(r0 + 8) * DMODEL + n) =
            make_float2(R.acc[nb].z + bb.x, R.acc[nb].w + bb.y);
    }
}

// ---------------------------------------------------------------------------
extern "C" void kernel_launch(void* const* d_in, const int* in_sizes, int n_in,
                              void* d_out, int out_size)
{
    const float* x     = (const float*)d_in[0];
    const float* W_qkv = (const float*)d_in[1];
    const float* b_qkv = (const float*)d_in[2];
    const float* W_out = (const float*)d_in[3];
    const float* b_out = (const float*)d_in[4];

    for (int i = 0; i < n_in; ++i) {
        switch (in_sizes[i]) {
            case MROWS * DMODEL:  x     = (const float*)d_in[i]; break;
            case DMODEL * QKVD:   W_qkv = (const float*)d_in[i]; break;
            case QKVD:            b_qkv = (const float*)d_in[i]; break;
            case DMODEL * DMODEL: W_out = (const float*)d_in[i]; break;
            case DMODEL:          b_out = (const float*)d_in[i]; break;
            default: break;
        }
    }
    float* out = (float*)d_out;
    (void)out_size;

    static bool attr_done = false;
    if (!attr_done) {
        cudaFuncSetAttribute(flash_mma,
                             cudaFuncAttributeMaxDynamicSharedMemorySize,
                             FL_SMEM);
        attr_done = true;
    }

    convert_x<<<MROWS, 256>>>(x);
    convert_wq<<<256, 256>>>(W_qkv);
    convert_wo<<<256, 256>>>(W_out);
    qkv_gemm_mma<<<dim3(QKVD / 128, MROWS / 128), 256>>>(b_qkv);
    presplit_v<<<dim3(SEQ / 64, NBH), 256>>>();
    flash_mma<<<NBH * 32 * NSPLIT, 128, FL_SMEM>>>();
    combine_o<<<(MROWS * DMODEL / 4) / 256, 256>>>();
    out_gemm_mma<<<dim3(DMODEL / 128, MROWS / 128), 256>>>(b_out, out);
}